// round 17
// baseline (speedup 1.0000x reference)
#include <cuda_runtime.h>
#include <cuda_bf16.h>

#define BB 16
#define SS 4096
#define DD 1024

#define GSPLIT 32      // split-K for the weight GEMVs
#define ESUM_TILES 64  // per-64-row-tile exp sums
#define CTX_TILES 16   // combined ctx partials (one per attn block)

// ---------------- scratch (device globals; no allocations) ----------------
__device__ float g_q_part[GSPLIT][BB * DD];
__device__ float g_q[BB * DD];
__device__ float g_qk[BB * DD];
__device__ float g_esum_part[BB][ESUM_TILES];
__device__ float g_ctx_part[CTX_TILES][BB * DD];
__device__ float g_out_part[GSPLIT][BB * DD];

// ---------------------------------------------------------------------------
// K1: split-K batched GEMV partials (R5/R16, validated).
// grid (8, 32) = 256 blocks, block 128.
// ---------------------------------------------------------------------------
__global__ void __launch_bounds__(128) gemv_part_kernel(const float* __restrict__ X,
                                                        const float* __restrict__ W,
                                                        float* __restrict__ part) {
    const int h  = blockIdx.x * 128 + threadIdx.x;
    const int IR = DD / GSPLIT;                     // 32
    const int i0 = blockIdx.y * IR;

    __shared__ float xs[BB][DD / GSPLIT];
    for (int t = threadIdx.x; t < BB * IR; t += 128) {
        int b = t >> 5, ii = t & 31;
        xs[b][ii] = X[b * DD + i0 + ii];
    }
    __syncthreads();

    float acc[BB];
#pragma unroll
    for (int b = 0; b < BB; b++) acc[b] = 0.f;

#pragma unroll 4
    for (int ii = 0; ii < IR; ii++) {
        float w = W[(size_t)(i0 + ii) * DD + h];
#pragma unroll
        for (int b = 0; b < BB; b++) acc[b] += xs[b][ii] * w;
    }

    float* p = part + (size_t)blockIdx.y * (BB * DD);
#pragma unroll
    for (int b = 0; b < BB; b++) p[b * DD + h] = acc[b];
}

// ---------------------------------------------------------------------------
// K2/K6: sum GSPLIT partials (R5/R16, validated). grid 128, block 128.
// ---------------------------------------------------------------------------
__global__ void __launch_bounds__(128) reduce32_kernel(const float* __restrict__ part,
                                                       float* __restrict__ out) {
    const int idx = blockIdx.x * 128 + threadIdx.x;
    float s = 0.f;
#pragma unroll
    for (int k = 0; k < GSPLIT; k++) s += part[(size_t)k * (BB * DD) + idx];
    out[idx] = s;
}

// ---------------------------------------------------------------------------
// K3: qk v2 (R13/R16, validated) — 2 rows per warp. grid 128, block 128.
// ---------------------------------------------------------------------------
__global__ void __launch_bounds__(128) qk_kernel(const float* __restrict__ Wk) {
    __shared__ __align__(16) float qs[BB][DD];   // 64 KB
    const int tid = threadIdx.x;

    for (int t = tid; t < BB * DD / 4; t += 128) {
        ((float4*)&qs[0][0])[t] = ((const float4*)g_q)[t];
    }
    __syncthreads();

    const int warp = tid >> 5;
    const int lane = tid & 31;
    const int r0 = blockIdx.x * 8 + warp * 2;
    const int r1 = r0 + 1;
    const float4* w0 = (const float4*)(Wk + (size_t)r0 * DD);
    const float4* w1 = (const float4*)(Wk + (size_t)r1 * DD);

    float acc0[BB], acc1[BB];
#pragma unroll
    for (int b = 0; b < BB; b++) { acc0[b] = 0.f; acc1[b] = 0.f; }

#pragma unroll
    for (int c = 0; c < DD / 4; c += 32) {
        float4 a4 = w0[c + lane];
        float4 b4 = w1[c + lane];
#pragma unroll
        for (int b = 0; b < BB; b++) {
            float4 q4 = ((const float4*)qs[b])[c + lane];
            acc0[b] += a4.x * q4.x + a4.y * q4.y + a4.z * q4.z + a4.w * q4.w;
            acc1[b] += b4.x * q4.x + b4.y * q4.y + b4.z * q4.z + b4.w * q4.w;
        }
    }
#pragma unroll
    for (int b = 0; b < BB; b++) {
        float v0 = acc0[b], v1 = acc1[b];
#pragma unroll
        for (int o = 16; o > 0; o >>= 1) {
            v0 += __shfl_down_sync(0xffffffffu, v0, o);
            v1 += __shfl_down_sync(0xffffffffu, v1, o);
        }
        if (lane == 0) {
            g_qk[b * DD + r0] = v0;
            g_qk[b * DD + r1] = v1;
        }
    }
}

// ---------------------------------------------------------------------------
// K4: fused attention — 4 tiles per block (grid 256), combined ctx partial.
// Same validated body as R14/R16, loop extended to 4 tiles; ctx_part now
// 16 slices (-16 MB write here, -16 MB read downstream).
// ---------------------------------------------------------------------------
__global__ void __launch_bounds__(256) attn_fused_kernel(const float* __restrict__ key,
                                                         const float* __restrict__ value) {
    const int b  = blockIdx.x >> 4;
    const int t0 = blockIdx.x & 15;
    const int warp = threadIdx.x >> 5;
    const int lane = threadIdx.x & 31;

    __shared__ __align__(16) float qk_s[DD];
    __shared__ float w_s[64];
    __shared__ float red[8];

    ((float4*)qk_s)[threadIdx.x] = ((const float4*)(g_qk + b * DD))[threadIdx.x];
    const float4* qrow = (const float4*)qk_s;

    float4 acc = make_float4(0.f, 0.f, 0.f, 0.f);   // persists across 4 tiles

#pragma unroll
    for (int q = 0; q < 4; q++) {
        const int tile = t0 + q * 16;
        const int s0 = tile * 64;
        __syncthreads();   // qk_s ready (q=0) / w_s no longer read (q>0)

        const float4* kbase = (const float4*)(key + ((size_t)b * SS + s0) * DD);

        // ---- Phase A: 2 groups of 4 rows per warp ----
        float esum = 0.f;
#pragma unroll
        for (int g = 0; g < 2; g++) {
            const int r = warp * 8 + g * 4;
            const float4* k0 = kbase + (size_t)(r + 0) * (DD / 4);
            const float4* k1 = kbase + (size_t)(r + 1) * (DD / 4);
            const float4* k2 = kbase + (size_t)(r + 2) * (DD / 4);
            const float4* k3 = kbase + (size_t)(r + 3) * (DD / 4);

            float a0 = 0.f, a1 = 0.f, a2 = 0.f, a3 = 0.f;
#pragma unroll
            for (int c = 0; c < DD / 4; c += 32) {
                float4 q4 = qrow[c + lane];
                float4 ka = __ldcs(&k0[c + lane]);
                float4 kb = __ldcs(&k1[c + lane]);
                float4 kc = __ldcs(&k2[c + lane]);
                float4 kd = __ldcs(&k3[c + lane]);
                a0 += ka.x * q4.x + ka.y * q4.y + ka.z * q4.z + ka.w * q4.w;
                a1 += kb.x * q4.x + kb.y * q4.y + kb.z * q4.z + kb.w * q4.w;
                a2 += kc.x * q4.x + kc.y * q4.y + kc.z * q4.z + kc.w * q4.w;
                a3 += kd.x * q4.x + kd.y * q4.y + kd.z * q4.z + kd.w * q4.w;
            }
#pragma unroll
            for (int o = 16; o > 0; o >>= 1) {
                a0 += __shfl_down_sync(0xffffffffu, a0, o);
                a1 += __shfl_down_sync(0xffffffffu, a1, o);
                a2 += __shfl_down_sync(0xffffffffu, a2, o);
                a3 += __shfl_down_sync(0xffffffffu, a3, o);
            }
            if (lane == 0) {
                float e0 = expf(a0 * 0.03125f);   // 1/sqrt(1024); bounded
                float e1 = expf(a1 * 0.03125f);
                float e2 = expf(a2 * 0.03125f);
                float e3 = expf(a3 * 0.03125f);
                w_s[r + 0] = e0; w_s[r + 1] = e1;
                w_s[r + 2] = e2; w_s[r + 3] = e3;
                esum += (e0 + e1) + (e2 + e3);
            }
        }
        if (lane == 0) red[warp] = esum;
        __syncthreads();

        if (threadIdx.x == 0) {
            float s = 0.f;
#pragma unroll
            for (int w = 0; w < 8; w++) s += red[w];
            g_esum_part[b][tile] = s;
        }

        // ---- Phase B: accumulate into persistent acc ----
        const float4* vbase = (const float4*)(value + ((size_t)b * SS + s0) * DD);
#pragma unroll 16
        for (int ss = 0; ss < 64; ss++) {
            float w = w_s[ss];
            float4 v = __ldcs(&vbase[(size_t)ss * (DD / 4) + threadIdx.x]);
            acc.x += w * v.x; acc.y += w * v.y; acc.z += w * v.z; acc.w += w * v.w;
        }
    }

    // single combined write (all 4 tiles)
    ((float4*)g_ctx_part[t0])[b * (DD / 4) + threadIdx.x] = acc;
}

// ---------------------------------------------------------------------------
// K5: out-GEMV with INLINE ctx reconstruction + softmax normalization
// (replaces norm_ctx + gemv_part pair). Algebra: out = inv[b] * (raw ctx)@Wv,
// so inv is applied at the accumulator write. esum summed in fixed j order.
// grid (8, 32) = 256 blocks, block 128.
// ---------------------------------------------------------------------------
__global__ void __launch_bounds__(128) gemv_ctx_kernel(const float* __restrict__ Wv,
                                                       float* __restrict__ part) {
    const int h  = blockIdx.x * 128 + threadIdx.x;
    const int IR = DD / GSPLIT;                     // 32
    const int i0 = blockIdx.y * IR;

    __shared__ float xs[BB][DD / GSPLIT];
    __shared__ float s_inv[BB];

    if (threadIdx.x < BB) {
        float e = 0.f;
#pragma unroll
        for (int j = 0; j < ESUM_TILES; j++) e += g_esum_part[threadIdx.x][j];
        s_inv[threadIdx.x] = 1.f / e;
    }
    for (int t = threadIdx.x; t < BB * IR; t += 128) {
        int b = t >> 5, ii = t & 31;
        float s = 0.f;
#pragma unroll
        for (int k = 0; k < CTX_TILES; k++) s += g_ctx_part[k][b * DD + i0 + ii];
        xs[b][ii] = s;
    }
    __syncthreads();

    float acc[BB];
#pragma unroll
    for (int b = 0; b < BB; b++) acc[b] = 0.f;

#pragma unroll 4
    for (int ii = 0; ii < IR; ii++) {
        float w = Wv[(size_t)(i0 + ii) * DD + h];
#pragma unroll
        for (int b = 0; b < BB; b++) acc[b] += xs[b][ii] * w;
    }

    float* p = part + (size_t)blockIdx.y * (BB * DD);
#pragma unroll
    for (int b = 0; b < BB; b++) p[b * DD + h] = acc[b] * s_inv[b];
}

// ---------------------------------------------------------------------------
extern "C" void kernel_launch(void* const* d_in, const int* in_sizes, int n_in,
                              void* d_out, int out_size) {
    const float* key   = (const float*)d_in[0];
    const float* query = (const float*)d_in[1];
    const float* value = (const float*)d_in[2];
    const float* Wk    = (const float*)d_in[3];
    const float* Wq    = (const float*)d_in[4];
    const float* Wv    = (const float*)d_in[5];
    float* out = (float*)d_out;

    float *d_q, *d_qpart, *d_opart;
    cudaGetSymbolAddress((void**)&d_q, g_q);
    cudaGetSymbolAddress((void**)&d_qpart, g_q_part);
    cudaGetSymbolAddress((void**)&d_opart, g_out_part);

    // q = query @ Wq
    gemv_part_kernel<<<dim3(DD / 128, GSPLIT), 128>>>(query, Wq, d_qpart);
    reduce32_kernel<<<BB * DD / 128, 128>>>(d_qpart, d_q);
    // qk[b] = Wk @ q[b]
    qk_kernel<<<128, 128>>>(Wk);
    // fused attention (4 tiles per block, combined ctx partials)
    attn_fused_kernel<<<256, 256>>>(key, value);
    // out partials = normalize(ctx) @ Wv   (ctx reconstructed inline)
    gemv_ctx_kernel<<<dim3(DD / 128, GSPLIT), 128>>>(Wv, d_opart);
    reduce32_kernel<<<BB * DD / 128, 128>>>(d_opart, out);
}